// round 5
// baseline (speedup 1.0000x reference)
#include <cuda_runtime.h>

// cost = where(0<=v<=1, A*exp(B*(1+v)) + C, OOB_COST), v = X[i*8+7]
// A=0.01, B=4.81, C=0.0, OOB=3.0
// Pure streaming kernel at the HBM roofline. Persistent one-wave grid-stride
// to eliminate wave-transition cost and cross-CTA L1tex-queue straggle.

__device__ __forceinline__ float penalize(float v) {
    float c = 0.01f * __expf(4.81f * (1.0f + v));
    return (v >= 0.0f && v <= 1.0f) ? c : 3.0f;
}

__global__ __launch_bounds__(256)
void penalizer_kernel(const float* __restrict__ X,
                      float* __restrict__ out,
                      int n) {
    const int stride_rows = gridDim.x * blockDim.x * 8;  // rows per grid-iteration
    int i = (blockIdx.x * blockDim.x + threadIdx.x) * 8;

    for (; i + 7 < n; i += stride_rows) {
        const float* p = X + (size_t)i * 8 + 7;
        // 8 independent evict-first loads, one 32B sector each (MLP=8)
        float v0 = __ldcs(p + 0 * 8);
        float v1 = __ldcs(p + 1 * 8);
        float v2 = __ldcs(p + 2 * 8);
        float v3 = __ldcs(p + 3 * 8);
        float v4 = __ldcs(p + 4 * 8);
        float v5 = __ldcs(p + 5 * 8);
        float v6 = __ldcs(p + 6 * 8);
        float v7 = __ldcs(p + 7 * 8);

        float4 r0, r1;
        r0.x = penalize(v0);
        r0.y = penalize(v1);
        r0.z = penalize(v2);
        r0.w = penalize(v3);
        r1.x = penalize(v4);
        r1.y = penalize(v5);
        r1.z = penalize(v6);
        r1.w = penalize(v7);

        __stcs(reinterpret_cast<float4*>(out + i), r0);
        __stcs(reinterpret_cast<float4*>(out + i + 4), r1);
    }

    // Scalar tail (never taken for n % 8 == 0, kept for generality)
    if (i < n) {
        for (int j = i; j < n; ++j) {
            float v = __ldcs(X + (size_t)j * 8 + 7);
            out[j] = penalize(v);
        }
    }
}

extern "C" void kernel_launch(void* const* d_in, const int* in_sizes, int n_in,
                              void* d_out, int out_size) {
    const float* X = (const float*)d_in[0];
    float* out = (float*)d_out;
    int n = out_size;  // one output per row; in_sizes[0] == n*8

    // One resident wave: 152 SMs on GB300, ~6 CTAs of 256 thr resident each.
    int threads = 256;
    int blocks = 152 * 6;  // 912 CTAs, grid-stride covers all rows
    penalizer_kernel<<<blocks, threads>>>(X, out, n);
}

// round 6
// speedup vs baseline: 1.2571x; 1.2571x over previous
#include <cuda_runtime.h>

// cost = where(0<=v<=1, A*exp(B*(1+v)) + C, OOB_COST), v = X[i*8+7]
// A=0.01, B=4.81, C=0.0, OOB=3.0
// Streaming kernel at HBM roofline. Big oversubscribed grid (backfill keeps
// LSU queues full). Block-strided lane-major row mapping: each LDG's 32 lanes
// hit 32 consecutive rows = 8 x 128B lines (minimal L1tex wavefronts),
// each STG is one fully-coalesced 128B line.

__device__ __forceinline__ float penalize(float v) {
    float c = 0.01f * __expf(4.81f * (1.0f + v));
    return (v >= 0.0f && v <= 1.0f) ? c : 3.0f;
}

__global__ __launch_bounds__(256)
void penalizer_kernel(const float* __restrict__ X,
                      float* __restrict__ out,
                      int n) {
    const int ROWS_PER_BLOCK = 256 * 8;
    int base = blockIdx.x * ROWS_PER_BLOCK + threadIdx.x;

    if (base + 256 * 7 < n) {
        // 8 front-batched evict-first loads; lanes consecutive -> coalesced lines
        float v[8];
#pragma unroll
        for (int j = 0; j < 8; ++j)
            v[j] = __ldcs(X + (size_t)(base + 256 * j) * 8 + 7);

#pragma unroll
        for (int j = 0; j < 8; ++j)
            __stcs(out + base + 256 * j, penalize(v[j]));
    } else {
        // Tail block: per-row guard (never taken when n % 2048 == 0)
#pragma unroll
        for (int j = 0; j < 8; ++j) {
            int r = base + 256 * j;
            if (r < n) {
                float vv = __ldcs(X + (size_t)r * 8 + 7);
                out[r] = penalize(vv);
            }
        }
    }
}

extern "C" void kernel_launch(void* const* d_in, const int* in_sizes, int n_in,
                              void* d_out, int out_size) {
    const float* X = (const float*)d_in[0];
    float* out = (float*)d_out;
    int n = out_size;  // one output per row; in_sizes[0] == n*8

    int threads = 256;
    int rows_per_block = threads * 8;
    int blocks = (n + rows_per_block - 1) / rows_per_block;  // 8192 for n=16.7M
    penalizer_kernel<<<blocks, threads>>>(X, out, n);
}